// round 11
// baseline (speedup 1.0000x reference)
#include <cuda_runtime.h>
#include <cuda_fp16.h>
#include <cstdint>

#define DT_STEP 0.01f
#define GRID_SMS 152
#define NUM_S32 4096                    // 131072 rows / 32
#define NTHREADS 512
#define NPAIRS 8
#define ROW_B 272                       // 128 f16 (256B) + 16B pad
#define T32 (32 * ROW_B)                // 32-row strip = 8704 B

#define S_W1  0
#define S_W2  (S_W1 + 128 * ROW_B)
#define S_B1  (S_W2 + 128 * ROW_B)
#define S_B2  (S_B1 + 512)
#define S_POP (S_B2 + 512)              // per-pair popped unit ids
#define S_Q   (S_POP + 512)
#define S_TOT (S_Q + NPAIRS * 2 * T32)  // 71168 + 139264 = 210432 B

__device__ unsigned int g_ctr;

__global__ void reset_ctr() { g_ctr = 0u; }

// ---------------- helpers ----------------
static __device__ __forceinline__ uint32_t smem_u32(const void* p) {
    uint32_t a;
    asm("{ .reg .u64 t; cvta.to.shared.u64 t, %1; cvt.u32.u64 %0, t; }" : "=r"(a) : "l"(p));
    return a;
}

static __device__ __forceinline__ uint32_t packhf(float a, float b) {
    __half2 t = __floats2half2_rn(a, b);   // .x in low 16 bits
    return *reinterpret_cast<uint32_t*>(&t);
}

static __device__ __forceinline__ float2 unpackhf(uint32_t v) {
    return __half22float2(*reinterpret_cast<__half2*>(&v));
}

static __device__ __forceinline__ float tanh_fast(float v) {
    float r;
    asm("tanh.approx.f32 %0, %1;" : "=f"(r) : "f"(v));
    return r;
}

static __device__ __forceinline__ void ldsm_x4(uint32_t* r, uint32_t addr) {
    asm volatile("ldmatrix.sync.aligned.m8n8.x4.shared.b16 {%0,%1,%2,%3}, [%4];"
                 : "=r"(r[0]), "=r"(r[1]), "=r"(r[2]), "=r"(r[3]) : "r"(addr));
}

static __device__ __forceinline__ void ldsm_x4_t(uint32_t* r, uint32_t addr) {
    asm volatile("ldmatrix.sync.aligned.m8n8.x4.trans.shared.b16 {%0,%1,%2,%3}, [%4];"
                 : "=r"(r[0]), "=r"(r[1]), "=r"(r[2]), "=r"(r[3]) : "r"(addr));
}

// f16 inputs, f16 accumulators: D/C = 2 b32 regs (4 halves)
static __device__ __forceinline__ void mma16816h(uint32_t* d, const uint32_t* a,
                                                 const uint32_t* b) {
    asm volatile("mma.sync.aligned.m16n8k16.row.col.f16.f16.f16.f16 "
                 "{%0,%1}, {%2,%3,%4,%5}, {%6,%7}, {%0,%1};"
                 : "+r"(d[0]), "+r"(d[1])
                 : "r"(a[0]), "r"(a[1]), "r"(a[2]), "r"(a[3]), "r"(b[0]), "r"(b[1]));
}

// 32x64 warp GEMM, f16 accum. acc[nt][mt][2]; live regs: afr 16 + b 4.
static __device__ __forceinline__ void gemm_32x64h(uint32_t abase, uint32_t wl,
                                                   uint32_t amBase, uint32_t acc[8][2][2]) {
    #pragma unroll
    for (int q = 0; q < 4; q++) {                 // k32 chunks
        uint32_t afr[2][2][4];                    // [kt][mt]
        #pragma unroll
        for (int kt = 0; kt < 2; kt++)
            #pragma unroll
            for (int mt = 0; mt < 2; mt++)
                ldsm_x4(afr[kt][mt], abase + amBase + (uint32_t)(mt * 16) * ROW_B
                                     + (uint32_t)(q * 64 + kt * 32));
        #pragma unroll
        for (int nt = 0; nt < 8; nt++) {
            uint32_t b[4];                        // k32 x n8
            ldsm_x4_t(b, wl + (uint32_t)q * (32 * ROW_B) + (uint32_t)nt * 16);
            #pragma unroll
            for (int mt = 0; mt < 2; mt++)
                #pragma unroll
                for (int kt = 0; kt < 2; kt++)
                    mma16816h(acc[nt][mt], afr[kt][mt], &b[kt * 2]);
        }
    }
}

// ---------------- kernel ----------------
__global__ void __launch_bounds__(NTHREADS, 1)
koopman_h16(const float* __restrict__ x, const float* __restrict__ W1,
            const float* __restrict__ b1, const float* __restrict__ W2,
            const float* __restrict__ b2, float* __restrict__ out)
{
    extern __shared__ char smem[];
    const uint32_t sb = smem_u32(smem);
    const int tid  = threadIdx.x;
    const int lane = tid & 31;
    const int w    = tid >> 5;          // 0..15
    const int pair = w >> 1;            // 0..7
    const int wp   = w & 1;             // N-half owner
    const int g    = lane >> 2;
    const int t2   = (lane & 3) * 2;
    const int barid = pair + 1;

    // ---- one-time: stage W1, W2 (f16, padded rows) + biases ----
    #pragma unroll
    for (int j = 0; j < 8; j++) {
        int idx = j * NTHREADS + tid;   // 4096 float4 chunks per matrix
        int r = idx >> 5, c4 = idx & 31;
        float4 wv = *(const float4*)(W1 + (size_t)r * 128 + c4 * 4);
        *(uint2*)(smem + S_W1 + r * ROW_B + c4 * 8) =
            make_uint2(packhf(wv.x, wv.y), packhf(wv.z, wv.w));
        float4 wv2 = *(const float4*)(W2 + (size_t)r * 128 + c4 * 4);
        *(uint2*)(smem + S_W2 + r * ROW_B + c4 * 8) =
            make_uint2(packhf(wv2.x, wv2.y), packhf(wv2.z, wv2.w));
    }
    if (tid < 128) {
        ((float*)(smem + S_B1))[tid] = b1[tid];
        ((float*)(smem + S_B2))[tid] = b2[tid];
    }
    __syncthreads();                    // only CTA-wide sync

    const uint32_t qoff = (uint32_t)(S_Q + pair * 2 * T32);   // x strip offset
    const uint32_t hoff = qoff + T32;                          // H strip offset
    const uint32_t wl1 = sb + S_W1 + (uint32_t)lane * ROW_B + (uint32_t)wp * 128;
    const uint32_t wl2 = sb + S_W2 + (uint32_t)lane * ROW_B + (uint32_t)wp * 128;
    const int cbase = wp * 64;
    const float* fb1 = (const float*)(smem + S_B1) + cbase + t2;
    const float* fb2 = (const float*)(smem + S_B2) + cbase + t2;
    volatile int* pop = (volatile int*)(smem + S_POP) + pair;

    const uint32_t amBase = (uint32_t)((lane & 7) + ((lane >> 3) & 1) * 8) * ROW_B
                          + (uint32_t)(lane >> 4) * 16;
    const int srow = wp * 16;           // this warp stages 16 rows

    // ---- pop first unit ----
    if (wp == 0 && lane == 0) *pop = (int)atomicAdd(&g_ctr, 1u);
    asm volatile("bar.sync %0, 64;" :: "r"(barid) : "memory");
    int s = *pop;

    while (s < NUM_S32) {
        const size_t rbase = (size_t)s * 32;

        // ---- stage this unit's x (f16), 16 rows per warp, coalesced ----
        {
            const float* xr = x + (rbase + (size_t)srow) * 128 + lane * 4;
            #pragma unroll
            for (int i = 0; i < 16; i++) {
                float4 v = *(const float4*)(xr + (size_t)i * 128);
                *(uint2*)(smem + qoff + (srow + i) * ROW_B + lane * 8) =
                    make_uint2(packhf(v.x, v.y), packhf(v.z, v.w));
            }
        }
        asm volatile("bar.sync %0, 64;" :: "r"(barid) : "memory");    // x ready

        // ---- GEMM1: acc = Xf16(32) @ W1(:, half), f16 accum ----
        uint32_t acc[8][2][2];
        #pragma unroll
        for (int nt = 0; nt < 8; nt++)
            #pragma unroll
            for (int mt = 0; mt < 2; mt++)
                { acc[nt][mt][0] = 0u; acc[nt][mt][1] = 0u; }
        gemm_32x64h(sb + qoff, wl1, amBase, acc);

        // ---- epilogue 1: H half = tanh(acc + b1) -> H strip (f16) ----
        #pragma unroll
        for (int nt = 0; nt < 8; nt++) {
            float2 bb = *(const float2*)(fb1 + nt * 8);
            int c = cbase + nt * 8 + t2;
            #pragma unroll
            for (int mt = 0; mt < 2; mt++) {
                float2 p = unpackhf(acc[nt][mt][0]);      // row mt*16+g
                float2 q = unpackhf(acc[nt][mt][1]);      // row mt*16+g+8
                uint32_t h0 = packhf(tanh_fast(p.x + bb.x), tanh_fast(p.y + bb.y));
                uint32_t h1 = packhf(tanh_fast(q.x + bb.x), tanh_fast(q.y + bb.y));
                *(uint32_t*)(smem + hoff + (mt * 16 + g) * ROW_B + c * 2) = h0;
                *(uint32_t*)(smem + hoff + (mt * 16 + g + 8) * ROW_B + c * 2) = h1;
            }
        }
        // pop next unit; same barrier publishes H and the popped id
        if (wp == 0 && lane == 0) *pop = (int)atomicAdd(&g_ctr, 1u);
        asm volatile("bar.sync %0, 64;" :: "r"(barid) : "memory");    // H + pop ready

        // ---- GEMM2: acc = H(32) @ W2(:, half), f16 accum ----
        #pragma unroll
        for (int nt = 0; nt < 8; nt++)
            #pragma unroll
            for (int mt = 0; mt < 2; mt++)
                { acc[nt][mt][0] = 0u; acc[nt][mt][1] = 0u; }
        gemm_32x64h(sb + hoff, wl2, amBase, acc);

        // ---- epilogue 2: rotation-scaling on exact fp32 x from gmem ----
        #pragma unroll
        for (int nt = 0; nt < 8; nt++) {
            int c = cbase + nt * 8 + t2;
            float2 bb = *(const float2*)(fb2 + nt * 8);
            #pragma unroll
            for (int mt = 0; mt < 2; mt++)
                #pragma unroll
                for (int half = 0; half < 2; half++) {
                    float2 p = unpackhf(acc[nt][mt][half]);
                    float mu = p.x + bb.x;
                    float om = p.y + bb.y;
                    size_t r = rbase + (size_t)(mt * 16 + g + half * 8);
                    float2 xv = *(const float2*)(x + r * 128 + c);
                    float z  = DT_STEP * mu;
                    float e  = fmaf(z, fmaf(z, fmaf(z, 1.f / 6.f, 0.5f), 1.f), 1.f);
                    float wv = DT_STEP * om;
                    float w2 = wv * wv;
                    float sn = wv * fmaf(w2, -1.f / 6.f, 1.f);
                    float cs = fmaf(w2, fmaf(w2, 1.f / 24.f, -0.5f), 1.f);
                    float2 o;
                    o.x = e * (cs * xv.x - sn * xv.y);
                    o.y = e * (sn * xv.x + cs * xv.y);
                    *(float2*)(out + r * 128 + c) = o;
                }
        }
        asm volatile("bar.sync %0, 64;" :: "r"(barid) : "memory");    // strips reusable
        s = *pop;
    }
}

// ---------------- launch ----------------
extern "C" void kernel_launch(void* const* d_in, const int* in_sizes, int n_in,
                              void* d_out, int out_size) {
    const float* x  = (const float*)d_in[0];
    const float* W1 = (const float*)d_in[1];
    const float* b1 = (const float*)d_in[2];
    const float* W2 = (const float*)d_in[3];
    const float* b2 = (const float*)d_in[4];
    float* out = (float*)d_out;

    cudaFuncSetAttribute(koopman_h16,
                         cudaFuncAttributeMaxDynamicSharedMemorySize, S_TOT);
    reset_ctr<<<1, 1>>>();
    koopman_h16<<<GRID_SMS, NTHREADS, S_TOT>>>(x, W1, b1, W2, b2, out);
}

// round 12
// speedup vs baseline: 1.2184x; 1.2184x over previous
#include <cuda_runtime.h>
#include <cuda_fp16.h>
#include <cstdint>

#define DT_STEP 0.01f
#define GRID_SMS 152
#define NUM_TILES 1024                  // 131072 rows / 128
#define ROW_B 272                       // 128 f16 (256B) + 16B pad
#define T16 (16 * ROW_B)                // 16-row strip = 4352 B

#define S_W1  0
#define S_W2  (S_W1 + 128 * ROW_B)
#define S_B1  (S_W2 + 128 * ROW_B)
#define S_B2  (S_B1 + 512)
#define S_P   (S_B2 + 512)              // 8 pairs x (x0, x1, H)
#define S_TOT (S_P + 8 * 3 * T16)       // 70656 + 104448 = 175104 B

// ---------------- helpers ----------------
static __device__ __forceinline__ uint32_t smem_u32(const void* p) {
    uint32_t a;
    asm("{ .reg .u64 t; cvta.to.shared.u64 t, %1; cvt.u32.u64 %0, t; }" : "=r"(a) : "l"(p));
    return a;
}

static __device__ __forceinline__ uint32_t packhf(float a, float b) {
    __half2 t = __floats2half2_rn(a, b);   // .x in low 16 bits
    return *reinterpret_cast<uint32_t*>(&t);
}

static __device__ __forceinline__ float2 unpackhf(uint32_t v) {
    return __half22float2(*reinterpret_cast<__half2*>(&v));
}

static __device__ __forceinline__ float tanh_fast(float v) {
    float r;
    asm("tanh.approx.f32 %0, %1;" : "=f"(r) : "f"(v));
    return r;
}

static __device__ __forceinline__ void ldsm_x4(uint32_t* r, uint32_t addr) {
    asm volatile("ldmatrix.sync.aligned.m8n8.x4.shared.b16 {%0,%1,%2,%3}, [%4];"
                 : "=r"(r[0]), "=r"(r[1]), "=r"(r[2]), "=r"(r[3]) : "r"(addr));
}

static __device__ __forceinline__ void ldsm_x4_t(uint32_t* r, uint32_t addr) {
    asm volatile("ldmatrix.sync.aligned.m8n8.x4.trans.shared.b16 {%0,%1,%2,%3}, [%4];"
                 : "=r"(r[0]), "=r"(r[1]), "=r"(r[2]), "=r"(r[3]) : "r"(addr));
}

// f16 inputs, f16 accumulators
static __device__ __forceinline__ void mma16816h(uint32_t* d, const uint32_t* a,
                                                 const uint32_t* b) {
    asm volatile("mma.sync.aligned.m16n8k16.row.col.f16.f16.f16.f16 "
                 "{%0,%1}, {%2,%3,%4,%5}, {%6,%7}, {%0,%1};"
                 : "+r"(d[0]), "+r"(d[1])
                 : "r"(a[0]), "r"(a[1]), "r"(a[2]), "r"(a[3]), "r"(b[0]), "r"(b[1]));
}

// 16x64 warp GEMM with software-pipelined B-ldsm (double-buffered bb).
static __device__ __forceinline__ void gemm16x64_pipe(const uint32_t afr[8][4], uint32_t wl,
                                                      uint32_t acc[8][2]) {
    uint32_t bb[2][4][4];
    #pragma unroll
    for (int q = 0; q < 4; q++)
        ldsm_x4_t(bb[0][q], wl + (uint32_t)q * (32 * ROW_B));
    #pragma unroll
    for (int nt = 0; nt < 8; nt++) {
        const int cur = nt & 1;
        if (nt < 7) {
            #pragma unroll
            for (int q = 0; q < 4; q++)
                ldsm_x4_t(bb[cur ^ 1][q], wl + (uint32_t)q * (32 * ROW_B)
                                             + (uint32_t)(nt + 1) * 16);
        }
        #pragma unroll
        for (int kt = 0; kt < 8; kt++)
            mma16816h(acc[nt], afr[kt], &bb[cur][kt >> 1][(kt & 1) * 2]);
    }
}

// ---------------- kernel ----------------
__global__ void __launch_bounds__(512, 1)
koopman_pipe(const float* __restrict__ x, const float* __restrict__ W1,
             const float* __restrict__ b1, const float* __restrict__ W2,
             const float* __restrict__ b2, float* __restrict__ out)
{
    extern __shared__ char smem[];
    const uint32_t sb = smem_u32(smem);
    const int tid  = threadIdx.x;
    const int lane = tid & 31;
    const int w    = tid >> 5;          // 0..15
    const int pair = w >> 1;            // 0..7
    const int wp   = w & 1;             // N-half owner
    const int g    = lane >> 2;
    const int t2   = (lane & 3) * 2;
    const int barid = pair + 1;

    // ---- one-time: stage W1, W2 (f16, padded rows) + biases ----
    #pragma unroll
    for (int j = 0; j < 8; j++) {
        int idx = j * 512 + tid;        // 4096 float4 chunks per matrix
        int r = idx >> 5, c4 = idx & 31;
        float4 wv = *(const float4*)(W1 + (size_t)r * 128 + c4 * 4);
        *(uint2*)(smem + S_W1 + r * ROW_B + c4 * 8) =
            make_uint2(packhf(wv.x, wv.y), packhf(wv.z, wv.w));
        float4 wv2 = *(const float4*)(W2 + (size_t)r * 128 + c4 * 4);
        *(uint2*)(smem + S_W2 + r * ROW_B + c4 * 8) =
            make_uint2(packhf(wv2.x, wv2.y), packhf(wv2.z, wv2.w));
    }
    if (tid < 128) {
        ((float*)(smem + S_B1))[tid] = b1[tid];
        ((float*)(smem + S_B2))[tid] = b2[tid];
    }
    __syncthreads();                    // only CTA-wide sync

    const uint32_t qoff = (uint32_t)(S_P + pair * 3 * T16);   // x strips (double buffer)
    const uint32_t hoff = qoff + 2 * T16;                      // H strip
    const uint32_t wl1 = sb + S_W1 + (uint32_t)lane * ROW_B + (uint32_t)wp * 128;
    const uint32_t wl2 = sb + S_W2 + (uint32_t)lane * ROW_B + (uint32_t)wp * 128;
    const int cbase = wp * 64;
    const float* fb1 = (const float*)(smem + S_B1) + cbase + t2;
    const float* fb2 = (const float*)(smem + S_B2) + cbase + t2;
    const uint32_t amRow = (uint32_t)((lane & 7) + ((lane >> 3) & 1) * 8) * ROW_B
                         + (uint32_t)(lane >> 4) * 16;
    const int srow = wp * 8;            // this warp stages 8 rows of the 16-row band

    // ---- stage first tile's band into buffer 0 ----
    {
        const float* xr = x + ((size_t)blockIdx.x * 128 + pair * 16 + srow) * 128 + lane * 4;
        #pragma unroll
        for (int i = 0; i < 8; i++) {
            float4 v = *(const float4*)(xr + (size_t)i * 128);
            *(uint2*)(smem + qoff + (srow + i) * ROW_B + lane * 8) =
                make_uint2(packhf(v.x, v.y), packhf(v.z, v.w));
        }
    }
    asm volatile("bar.sync %0, 64;" :: "r"(barid) : "memory");

    int buf = 0;
    for (int t = blockIdx.x; t < NUM_TILES; t += GRID_SMS) {
        const size_t rowbase = (size_t)t * 128 + pair * 16;
        const uint32_t xoff  = qoff + (uint32_t)buf * T16;
        const uint32_t xoff2 = qoff + (uint32_t)(buf ^ 1) * T16;
        const bool hn = (t + GRID_SMS < NUM_TILES);
        const float* xnp = x + (((size_t)(t + GRID_SMS) * 128) + pair * 16 + srow) * 128
                         + lane * 4;

        // early LDG of next tile's first 4 rows (latency hides under GEMM1)
        float4 v[4];
        if (hn) {
            #pragma unroll
            for (int i = 0; i < 4; i++) v[i] = *(const float4*)(xnp + (size_t)i * 128);
        }

        // ---- A-frags + GEMM1: acc = X(band) @ W1(:, half) ----
        uint32_t afr[8][4];
        #pragma unroll
        for (int kt = 0; kt < 8; kt++)
            ldsm_x4(afr[kt], sb + xoff + amRow + (uint32_t)kt * 32);

        uint32_t acc[8][2];
        #pragma unroll
        for (int nt = 0; nt < 8; nt++) { acc[nt][0] = 0u; acc[nt][1] = 0u; }
        gemm16x64_pipe(afr, wl1, acc);

        // ---- stage next tile's band into the other buffer ----
        if (hn) {
            #pragma unroll
            for (int i = 0; i < 4; i++)
                *(uint2*)(smem + xoff2 + (srow + i) * ROW_B + lane * 8) =
                    make_uint2(packhf(v[i].x, v[i].y), packhf(v[i].z, v[i].w));
            #pragma unroll
            for (int i = 4; i < 8; i++) {
                float4 vv = *(const float4*)(xnp + (size_t)i * 128);
                *(uint2*)(smem + xoff2 + (srow + i) * ROW_B + lane * 8) =
                    make_uint2(packhf(vv.x, vv.y), packhf(vv.z, vv.w));
            }
        }

        // ---- epilogue 1: H half = tanh(acc + b1) -> H strip ----
        #pragma unroll
        for (int nt = 0; nt < 8; nt++) {
            float2 bb = *(const float2*)(fb1 + nt * 8);
            int c = cbase + nt * 8 + t2;
            float2 p = unpackhf(acc[nt][0]);      // row g
            float2 q = unpackhf(acc[nt][1]);      // row g+8
            *(uint32_t*)(smem + hoff + g * ROW_B + c * 2) =
                packhf(tanh_fast(p.x + bb.x), tanh_fast(p.y + bb.y));
            *(uint32_t*)(smem + hoff + (g + 8) * ROW_B + c * 2) =
                packhf(tanh_fast(q.x + bb.x), tanh_fast(q.y + bb.y));
        }
        asm volatile("bar.sync %0, 64;" :: "r"(barid) : "memory");   // H + next-x ready

        // ---- GEMM2: acc = H(band) @ W2(:, half) ----
        #pragma unroll
        for (int kt = 0; kt < 8; kt++)
            ldsm_x4(afr[kt], sb + hoff + amRow + (uint32_t)kt * 32);
        #pragma unroll
        for (int nt = 0; nt < 8; nt++) { acc[nt][0] = 0u; acc[nt][1] = 0u; }
        gemm16x64_pipe(afr, wl2, acc);

        // ---- epilogue 2: rotation-scaling on exact fp32 x from gmem ----
        #pragma unroll
        for (int nt = 0; nt < 8; nt++) {
            int c = cbase + nt * 8 + t2;
            float2 bb = *(const float2*)(fb2 + nt * 8);
            #pragma unroll
            for (int half = 0; half < 2; half++) {
                float2 p = unpackhf(acc[nt][half]);
                float mu = p.x + bb.x;
                float om = p.y + bb.y;
                size_t r = rowbase + (size_t)(g + half * 8);
                float2 xv = *(const float2*)(x + r * 128 + c);
                float z  = DT_STEP * mu;
                float e  = fmaf(z, fmaf(z, fmaf(z, 1.f / 6.f, 0.5f), 1.f), 1.f);
                float wv = DT_STEP * om;
                float w2 = wv * wv;
                float sn = wv * fmaf(w2, -1.f / 6.f, 1.f);
                float cs = fmaf(w2, fmaf(w2, 1.f / 24.f, -0.5f), 1.f);
                float2 o;
                o.x = e * (cs * xv.x - sn * xv.y);
                o.y = e * (sn * xv.x + cs * xv.y);
                *(float2*)(out + r * 128 + c) = o;
            }
        }
        asm volatile("bar.sync %0, 64;" :: "r"(barid) : "memory");   // H strip reusable
        buf ^= 1;
    }
}

// ---------------- launch ----------------
extern "C" void kernel_launch(void* const* d_in, const int* in_sizes, int n_in,
                              void* d_out, int out_size) {
    const float* x  = (const float*)d_in[0];
    const float* W1 = (const float*)d_in[1];
    const float* b1 = (const float*)d_in[2];
    const float* W2 = (const float*)d_in[3];
    const float* b2 = (const float*)d_in[4];
    float* out = (float*)d_out;

    cudaFuncSetAttribute(koopman_pipe,
                         cudaFuncAttributeMaxDynamicSharedMemorySize, S_TOT);
    koopman_pipe<<<GRID_SMS, 512, S_TOT>>>(x, W1, b1, W2, b2, out);
}

// round 13
// speedup vs baseline: 1.4765x; 1.2118x over previous
#include <cuda_runtime.h>
#include <cuda_fp16.h>
#include <cstdint>

#define DT_STEP 0.01f
#define GRID_SMS 152
#define NUM_TILES 1024                  // 131072 rows / 128
#define ROW_B 272                       // 128 f16 (256B) + 16B pad
#define T16 (16 * ROW_B)                // 16-row strip = 4352 B

#define S_W1  0
#define S_W2  (S_W1 + 128 * ROW_B)
#define S_B1  (S_W2 + 128 * ROW_B)
#define S_B2  (S_B1 + 512)
#define S_P   (S_B2 + 512)              // 8 pairs x (x0, x1, H)
#define S_TOT (S_P + 8 * 3 * T16)       // 70656 + 104448 = 175104 B

// ---------------- helpers ----------------
static __device__ __forceinline__ uint32_t smem_u32(const void* p) {
    uint32_t a;
    asm("{ .reg .u64 t; cvta.to.shared.u64 t, %1; cvt.u32.u64 %0, t; }" : "=r"(a) : "l"(p));
    return a;
}

static __device__ __forceinline__ uint32_t packhf(float a, float b) {
    __half2 t = __floats2half2_rn(a, b);   // .x in low 16 bits
    return *reinterpret_cast<uint32_t*>(&t);
}

static __device__ __forceinline__ float2 unpackhf(uint32_t v) {
    return __half22float2(*reinterpret_cast<__half2*>(&v));
}

static __device__ __forceinline__ float tanh_fast(float v) {
    float r;
    asm("tanh.approx.f32 %0, %1;" : "=f"(r) : "f"(v));
    return r;
}

static __device__ __forceinline__ void ldsm_x4(uint32_t* r, uint32_t addr) {
    asm volatile("ldmatrix.sync.aligned.m8n8.x4.shared.b16 {%0,%1,%2,%3}, [%4];"
                 : "=r"(r[0]), "=r"(r[1]), "=r"(r[2]), "=r"(r[3]) : "r"(addr));
}

static __device__ __forceinline__ void ldsm_x4_t(uint32_t* r, uint32_t addr) {
    asm volatile("ldmatrix.sync.aligned.m8n8.x4.trans.shared.b16 {%0,%1,%2,%3}, [%4];"
                 : "=r"(r[0]), "=r"(r[1]), "=r"(r[2]), "=r"(r[3]) : "r"(addr));
}

// f16 inputs, f16 accumulators
static __device__ __forceinline__ void mma16816h(uint32_t* d, const uint32_t* a,
                                                 const uint32_t* b) {
    asm volatile("mma.sync.aligned.m16n8k16.row.col.f16.f16.f16.f16 "
                 "{%0,%1}, {%2,%3,%4,%5}, {%6,%7}, {%0,%1};"
                 : "+r"(d[0]), "+r"(d[1])
                 : "r"(a[0]), "r"(a[1]), "r"(a[2]), "r"(a[3]), "r"(b[0]), "r"(b[1]));
}

// 16x64 warp GEMM with software-pipelined B-ldsm (double-buffered bb).
static __device__ __forceinline__ void gemm16x64_pipe(const uint32_t afr[8][4], uint32_t wl,
                                                      uint32_t acc[8][2]) {
    uint32_t bb[2][4][4];
    #pragma unroll
    for (int q = 0; q < 4; q++)
        ldsm_x4_t(bb[0][q], wl + (uint32_t)q * (32 * ROW_B));
    #pragma unroll
    for (int nt = 0; nt < 8; nt++) {
        const int cur = nt & 1;
        if (nt < 7) {
            #pragma unroll
            for (int q = 0; q < 4; q++)
                ldsm_x4_t(bb[cur ^ 1][q], wl + (uint32_t)q * (32 * ROW_B)
                                             + (uint32_t)(nt + 1) * 16);
        }
        #pragma unroll
        for (int kt = 0; kt < 8; kt++)
            mma16816h(acc[nt], afr[kt], &bb[cur][kt >> 1][(kt & 1) * 2]);
    }
}

// ---------------- kernel ----------------
__global__ void __launch_bounds__(512, 1)
koopman_coal(const float* __restrict__ x, const float* __restrict__ W1,
             const float* __restrict__ b1, const float* __restrict__ W2,
             const float* __restrict__ b2, float* __restrict__ out)
{
    extern __shared__ char smem[];
    const uint32_t sb = smem_u32(smem);
    const int tid  = threadIdx.x;
    const int lane = tid & 31;
    const int w    = tid >> 5;          // 0..15
    const int pair = w >> 1;            // 0..7
    const int wp   = w & 1;             // N-half owner
    const int g    = lane >> 2;
    const int t2   = (lane & 3) * 2;
    const int barid = pair + 1;

    // ---- one-time: stage W1, W2 (f16, padded rows) + biases ----
    #pragma unroll
    for (int j = 0; j < 8; j++) {
        int idx = j * 512 + tid;        // 4096 float4 chunks per matrix
        int r = idx >> 5, c4 = idx & 31;
        float4 wv = *(const float4*)(W1 + (size_t)r * 128 + c4 * 4);
        *(uint2*)(smem + S_W1 + r * ROW_B + c4 * 8) =
            make_uint2(packhf(wv.x, wv.y), packhf(wv.z, wv.w));
        float4 wv2 = *(const float4*)(W2 + (size_t)r * 128 + c4 * 4);
        *(uint2*)(smem + S_W2 + r * ROW_B + c4 * 8) =
            make_uint2(packhf(wv2.x, wv2.y), packhf(wv2.z, wv2.w));
    }
    if (tid < 128) {
        ((float*)(smem + S_B1))[tid] = b1[tid];
        ((float*)(smem + S_B2))[tid] = b2[tid];
    }
    __syncthreads();                    // only CTA-wide sync

    const uint32_t qoff = (uint32_t)(S_P + pair * 3 * T16);   // x strips (double buffer)
    const uint32_t hoff = qoff + 2 * T16;                      // H strip
    const uint32_t wl1 = sb + S_W1 + (uint32_t)lane * ROW_B + (uint32_t)wp * 128;
    const uint32_t wl2 = sb + S_W2 + (uint32_t)lane * ROW_B + (uint32_t)wp * 128;
    const int cbase = wp * 64;
    const float* fb1 = (const float*)(smem + S_B1) + cbase + t2;
    // coalesced-epilogue bias: cols 4*lane .. 4*lane+3
    const float4 bq = *(const float4*)((const float*)(smem + S_B2) + lane * 4);
    const uint32_t amRow = (uint32_t)((lane & 7) + ((lane >> 3) & 1) * 8) * ROW_B
                         + (uint32_t)(lane >> 4) * 16;
    const int srow = wp * 8;            // this warp stages 8 rows of the 16-row band

    // ---- stage first tile's band into buffer 0 ----
    {
        const float* xr = x + ((size_t)blockIdx.x * 128 + pair * 16 + srow) * 128 + lane * 4;
        #pragma unroll
        for (int i = 0; i < 8; i++) {
            float4 v = *(const float4*)(xr + (size_t)i * 128);
            *(uint2*)(smem + qoff + (srow + i) * ROW_B + lane * 8) =
                make_uint2(packhf(v.x, v.y), packhf(v.z, v.w));
        }
    }
    asm volatile("bar.sync %0, 64;" :: "r"(barid) : "memory");

    int buf = 0;
    for (int t = blockIdx.x; t < NUM_TILES; t += GRID_SMS) {
        const size_t rowbase = (size_t)t * 128 + pair * 16;
        const uint32_t xoff  = qoff + (uint32_t)buf * T16;
        const uint32_t xoff2 = qoff + (uint32_t)(buf ^ 1) * T16;
        const bool hn = (t + GRID_SMS < NUM_TILES);
        const float* xnp = x + (((size_t)(t + GRID_SMS) * 128) + pair * 16 + srow) * 128
                         + lane * 4;

        // early LDG of next tile's first 4 rows (latency hides under GEMM1)
        float4 v[4];
        if (hn) {
            #pragma unroll
            for (int i = 0; i < 4; i++) v[i] = *(const float4*)(xnp + (size_t)i * 128);
        }

        // ---- A-frags + GEMM1: acc = X(band) @ W1(:, half) ----
        uint32_t afr[8][4];
        #pragma unroll
        for (int kt = 0; kt < 8; kt++)
            ldsm_x4(afr[kt], sb + xoff + amRow + (uint32_t)kt * 32);

        uint32_t acc[8][2];
        #pragma unroll
        for (int nt = 0; nt < 8; nt++) { acc[nt][0] = 0u; acc[nt][1] = 0u; }
        gemm16x64_pipe(afr, wl1, acc);

        // ---- stage next tile's band into the other buffer ----
        if (hn) {
            #pragma unroll
            for (int i = 0; i < 4; i++)
                *(uint2*)(smem + xoff2 + (srow + i) * ROW_B + lane * 8) =
                    make_uint2(packhf(v[i].x, v[i].y), packhf(v[i].z, v[i].w));
            #pragma unroll
            for (int i = 4; i < 8; i++) {
                float4 vv = *(const float4*)(xnp + (size_t)i * 128);
                *(uint2*)(smem + xoff2 + (srow + i) * ROW_B + lane * 8) =
                    make_uint2(packhf(vv.x, vv.y), packhf(vv.z, vv.w));
            }
        }

        // ---- epilogue 1: H half = tanh(acc + b1) -> H strip ----
        #pragma unroll
        for (int nt = 0; nt < 8; nt++) {
            float2 bb = *(const float2*)(fb1 + nt * 8);
            int c = cbase + nt * 8 + t2;
            float2 p = unpackhf(acc[nt][0]);      // row g
            float2 q = unpackhf(acc[nt][1]);      // row g+8
            *(uint32_t*)(smem + hoff + g * ROW_B + c * 2) =
                packhf(tanh_fast(p.x + bb.x), tanh_fast(p.y + bb.y));
            *(uint32_t*)(smem + hoff + (g + 8) * ROW_B + c * 2) =
                packhf(tanh_fast(q.x + bb.x), tanh_fast(q.y + bb.y));
        }
        asm volatile("bar.sync %0, 64;" :: "r"(barid) : "memory");   // H + next-x ready

        // ---- GEMM2: acc = H(band) @ W2(:, half) ----
        #pragma unroll
        for (int kt = 0; kt < 8; kt++)
            ldsm_x4(afr[kt], sb + hoff + amRow + (uint32_t)kt * 32);
        #pragma unroll
        for (int nt = 0; nt < 8; nt++) { acc[nt][0] = 0u; acc[nt][1] = 0u; }
        gemm16x64_pipe(afr, wl2, acc);

        // ---- exchange: raw f16 (mu,omega) pairs -> dead current-x strip ----
        // word index p = wp*32 + nt*4 + (lane&3); banks 4g+(lane&3): conflict-free
        #pragma unroll
        for (int nt = 0; nt < 8; nt++) {
            uint32_t po = (uint32_t)((cbase >> 1) + nt * 4 + (lane & 3)) * 4;
            *(uint32_t*)(smem + xoff + g * ROW_B + po) = acc[nt][0];
            *(uint32_t*)(smem + xoff + (g + 8) * ROW_B + po) = acc[nt][1];
        }
        asm volatile("bar.sync %0, 64;" :: "r"(barid) : "memory");   // exchange ready

        // ---- epilogue 2 (coalesced): rows wp*8..wp*8+7, full 128 cols ----
        #pragma unroll
        for (int i = 0; i < 8; i++) {
            int r = wp * 8 + i;
            uint2 mw = *(const uint2*)(smem + xoff + r * ROW_B + lane * 8);
            const float* xrow = x + (rowbase + (size_t)r) * 128;
            float4 xv = *(const float4*)(xrow + lane * 4);
            float2 p0 = unpackhf(mw.x);
            float2 p1 = unpackhf(mw.y);
            float mu0 = p0.x + bq.x, om0 = p0.y + bq.y;
            float mu1 = p1.x + bq.z, om1 = p1.y + bq.w;
            float z0  = DT_STEP * mu0, z1 = DT_STEP * mu1;
            float e0  = fmaf(z0, fmaf(z0, fmaf(z0, 1.f / 6.f, 0.5f), 1.f), 1.f);
            float e1  = fmaf(z1, fmaf(z1, fmaf(z1, 1.f / 6.f, 0.5f), 1.f), 1.f);
            float w0  = DT_STEP * om0, w1 = DT_STEP * om1;
            float w0s = w0 * w0, w1s = w1 * w1;
            float sn0 = w0 * fmaf(w0s, -1.f / 6.f, 1.f);
            float sn1 = w1 * fmaf(w1s, -1.f / 6.f, 1.f);
            float cs0 = fmaf(w0s, fmaf(w0s, 1.f / 24.f, -0.5f), 1.f);
            float cs1 = fmaf(w1s, fmaf(w1s, 1.f / 24.f, -0.5f), 1.f);
            float4 o;
            o.x = e0 * (cs0 * xv.x - sn0 * xv.y);
            o.y = e0 * (sn0 * xv.x + cs0 * xv.y);
            o.z = e1 * (cs1 * xv.z - sn1 * xv.w);
            o.w = e1 * (sn1 * xv.z + cs1 * xv.w);
            *(float4*)(out + (rowbase + (size_t)r) * 128 + lane * 4) = o;
        }
        asm volatile("bar.sync %0, 64;" :: "r"(barid) : "memory");   // strips reusable
        buf ^= 1;
    }
}

// ---------------- launch ----------------
extern "C" void kernel_launch(void* const* d_in, const int* in_sizes, int n_in,
                              void* d_out, int out_size) {
    const float* x  = (const float*)d_in[0];
    const float* W1 = (const float*)d_in[1];
    const float* b1 = (const float*)d_in[2];
    const float* W2 = (const float*)d_in[3];
    const float* b2 = (const float*)d_in[4];
    float* out = (float*)d_out;

    cudaFuncSetAttribute(koopman_coal,
                         cudaFuncAttributeMaxDynamicSharedMemorySize, S_TOT);
    koopman_coal<<<GRID_SMS, 512, S_TOT>>>(x, W1, b1, W2, b2, out);
}